// round 8
// baseline (speedup 1.0000x reference)
#include <cuda_runtime.h>
#include <math.h>

#define NMAX 200000
#define HID 64
#define FIN 128
#define NCLS 40
#define BKT 64   // neighbor bucket capacity per node

// ---------- scratch ----------
__device__ float g_h[NMAX * HID];    // hidden buffer A
__device__ float g_hb[NMAX * HID];   // hidden buffer B (double buffer)
__device__ float g_x1[NMAX * HID];   // x_first
__device__ int   g_cnt[NMAX];        // neighbor count (non-self in-degree)
__device__ int   g_bkt[NMAX * BKT];  // neighbor lists

// ---------- f32x2 helpers ----------
__device__ __forceinline__ unsigned long long pack2(float a, float b) {
    unsigned long long r;
    asm("mov.b64 %0, {%1, %2};" : "=l"(r) : "f"(a), "f"(b));
    return r;
}
__device__ __forceinline__ void unpack2(unsigned long long v, float& a, float& b) {
    asm("mov.b64 {%0, %1}, %2;" : "=f"(a), "=f"(b) : "l"(v));
}
__device__ __forceinline__ void ffma2(unsigned long long& d, unsigned long long a,
                                      unsigned long long b) {
    asm("fma.rn.f32x2 %0, %1, %2, %0;" : "+l"(d) : "l"(a), "l"(b));
}

// ---------- zero counters ----------
__global__ void k_zero(int N) {
    int i = blockIdx.x * blockDim.x + threadIdx.x;
    if (i < N) g_cnt[i] = 0;
}

// ---------- single-pass bucket build: 2 edges per thread ----------
__global__ __launch_bounds__(256) void k_bucket(const int* __restrict__ src,
                                                const int* __restrict__ dst, int E) {
    int t = blockIdx.x * blockDim.x + threadIdx.x;
    int e = t * 2;
    if (e >= E) return;
    int2 s2 = *(const int2*)&src[e];
    int2 d2 = *(const int2*)&dst[e];
    if (s2.x != d2.x) {
        int pos = atomicAdd(&g_cnt[d2.x], 1);
        if (pos < BKT) g_bkt[d2.x * BKT + pos] = s2.x;
    }
    if (e + 1 < E && s2.y != d2.y) {
        int pos = atomicAdd(&g_cnt[d2.y], 1);
        if (pos < BKT) g_bkt[d2.y * BKT + pos] = s2.y;
    }
}

// ---------- h = relu(x @ W1 + b1); seed x_first (64-row tile) ----------
__global__ __launch_bounds__(256) void k_gemm1(const float* __restrict__ x,
                                               const float* __restrict__ W1,
                                               const float* __restrict__ b1, int N) {
    extern __shared__ float sm[];
    float* xs = sm;                  // 64 x 128
    float* ws = sm + 64 * 128;       // 128 x 64
    const int tid = threadIdx.x;
    const int row0 = blockIdx.x * 64;

    for (int i = tid; i < (FIN * HID) / 4; i += 256)
        ((float4*)ws)[i] = ((const float4*)W1)[i];
    {
        int r = tid >> 5;            // 0..7
        int c4 = tid & 31;           // float4 col
        for (int j = 0; j < 8; j++) {
            int rr = r + j * 8;
            int g = row0 + rr;
            float4 v = (g < N) ? ((const float4*)x)[(size_t)g * 32 + c4]
                               : make_float4(0.f, 0.f, 0.f, 0.f);
            *(float4*)&xs[rr * 128 + c4 * 4] = v;
        }
    }
    __syncthreads();

    const int tr = tid >> 4, tc = tid & 15;
    const int r0 = tr * 4, c0 = tc * 4;
    unsigned long long acc2[4][2];
#pragma unroll
    for (int i = 0; i < 4; i++) { acc2[i][0] = 0ULL; acc2[i][1] = 0ULL; }

#pragma unroll 4
    for (int k = 0; k < FIN; k++) {
        ulonglong2 b2 = *(const ulonglong2*)&ws[k * HID + c0];
#pragma unroll
        for (int i = 0; i < 4; i++) {
            float a = xs[(r0 + i) * 128 + k];
            unsigned long long a2 = pack2(a, a);
            ffma2(acc2[i][0], a2, b2.x);
            ffma2(acc2[i][1], a2, b2.y);
        }
    }

    float4 bb = *(const float4*)&b1[c0];
#pragma unroll
    for (int i = 0; i < 4; i++) {
        int g = row0 + r0 + i;
        if (g < N) {
            float4 o;
            unpack2(acc2[i][0], o.x, o.y);
            unpack2(acc2[i][1], o.z, o.w);
            o.x = fmaxf(o.x + bb.x, 0.f);
            o.y = fmaxf(o.y + bb.y, 0.f);
            o.z = fmaxf(o.z + bb.z, 0.f);
            o.w = fmaxf(o.w + bb.w, 0.f);
            size_t idx = (size_t)g * 16 + (c0 >> 2);
            ((float4*)g_h)[idx] = o;
            ((float4*)g_x1)[idx] = o;
        }
    }
}

// ---------- fused layer (64-row tile, reg-capped for occupancy) ----------
__global__ __launch_bounds__(256, 6) void k_layer(const float* __restrict__ h_in,
                                                  float* __restrict__ h_out,
                                                  const float* __restrict__ relW,
                                                  const float* __restrict__ relb,
                                                  const float* __restrict__ fuse,
                                                  int layer, int N) {
    extern __shared__ float sm[];
    float* as = sm;                    // 64 x 64 (agg tile)
    float* wsm = sm + 64 * 64;         // 64 x 64
    float* bsm = wsm + 64 * 64;        // 64
    int* dsm = (int*)(bsm + 64);       // 64
    const float* W5 = relW + ((size_t)(layer * 6 + 5)) * 64 * 64;
    const float* b5 = relb + (size_t)(layer * 6 + 5) * 64;
    const int tid = threadIdx.x;
    const int row0 = blockIdx.x * 64;

    for (int i = tid; i < (64 * 64) / 4; i += 256)
        ((float4*)wsm)[i] = ((const float4*)W5)[i];
    if (tid < 64) {
        bsm[tid] = b5[tid];
        int g = row0 + tid;
        dsm[tid] = (g < N) ? __ldg(&g_cnt[g]) : 0;
    }

    // gather phase: half-warp per node, int4 index loads, 4-row value batches
    {
        const int hw = tid >> 4;    // 0..15
        const int c = tid & 15;     // float4 col
        const float4* h4 = (const float4*)h_in;
        for (int j = 0; j < 4; j++) {
            int rr = hw + j * 16;
            int g = row0 + rr;
            float4 acc = make_float4(0.f, 0.f, 0.f, 0.f);
            if (g < N) {
                acc = h4[(size_t)g * 16 + c];  // self
                const int4* nb4 = (const int4*)&g_bkt[g * BKT];
                int cnt = min(__ldg(&g_cnt[g]), BKT);
                int i = 0;
                for (; i + 4 <= cnt; i += 4) {
                    int4 s4 = __ldg(&nb4[i >> 2]);
                    float4 a = h4[(size_t)s4.x * 16 + c];
                    float4 b = h4[(size_t)s4.y * 16 + c];
                    float4 d = h4[(size_t)s4.z * 16 + c];
                    float4 e = h4[(size_t)s4.w * 16 + c];
                    acc.x += (a.x + b.x) + (d.x + e.x);
                    acc.y += (a.y + b.y) + (d.y + e.y);
                    acc.z += (a.z + b.z) + (d.z + e.z);
                    acc.w += (a.w + b.w) + (d.w + e.w);
                }
                if (i < cnt) {
                    int4 s4 = __ldg(&nb4[i >> 2]);  // bucket rows are BKT-padded; safe
                    int rem = cnt - i;
                    float4 a = h4[(size_t)s4.x * 16 + c];
                    acc.x += a.x; acc.y += a.y; acc.z += a.z; acc.w += a.w;
                    if (rem > 1) {
                        float4 b = h4[(size_t)s4.y * 16 + c];
                        acc.x += b.x; acc.y += b.y; acc.z += b.z; acc.w += b.w;
                    }
                    if (rem > 2) {
                        float4 d = h4[(size_t)s4.z * 16 + c];
                        acc.x += d.x; acc.y += d.y; acc.z += d.z; acc.w += d.w;
                    }
                }
            }
            *(float4*)&as[rr * 64 + c * 4] = acc;
        }
    }
    __syncthreads();

    const int tr = tid >> 4, tc = tid & 15;
    const int r0 = tr * 4, c0 = tc * 4;
    unsigned long long acc2[4][2];
#pragma unroll
    for (int i = 0; i < 4; i++) { acc2[i][0] = 0ULL; acc2[i][1] = 0ULL; }

#pragma unroll 4
    for (int k = 0; k < 64; k++) {
        ulonglong2 b2 = *(const ulonglong2*)&wsm[k * 64 + c0];
#pragma unroll
        for (int i = 0; i < 4; i++) {
            float a = as[(r0 + i) * 64 + k];
            unsigned long long a2 = pack2(a, a);
            ffma2(acc2[i][0], a2, b2.x);
            ffma2(acc2[i][1], a2, b2.y);
        }
    }

    float fv = fuse[layer];
    float4 bb = *(float4*)&bsm[c0];
#pragma unroll
    for (int i = 0; i < 4; i++) {
        int rr = r0 + i;
        int g = row0 + rr;
        if (g < N && dsm[rr] >= 5) {
            size_t idx = (size_t)g * 16 + (c0 >> 2);
            float4 xf = ((const float4*)g_x1)[idx];
            float4 o;
            unpack2(acc2[i][0], o.x, o.y);
            unpack2(acc2[i][1], o.z, o.w);
            o.x = o.x + bb.x + fv * xf.x;
            o.y = o.y + bb.y + fv * xf.y;
            o.z = o.z + bb.z + fv * xf.z;
            o.w = o.w + bb.w + fv * xf.w;
            ((float4*)h_out)[idx] = o;
        }
    }

    // inline fixup for rare deg<5 nodes (agg already in smem)
    if (tid < 64) {
        int g = row0 + tid;
        int d = dsm[tid];
        if (g < N && d < 5) {
            const float* W = relW + ((size_t)(layer * 6 + d)) * 64 * 64;
            const float* b = relb + (size_t)(layer * 6 + d) * 64;
            const float* arow = &as[tid * 64];
            for (int o = 0; o < 64; o++) {
                float s = b[o];
#pragma unroll 8
                for (int k = 0; k < 64; k++) s += arow[k] * W[k * 64 + o];
                h_out[(size_t)g * 64 + o] = s + fv * g_x1[(size_t)g * 64 + o];
            }
        }
    }
}

// ---------- output: log_softmax(h @ Wout + bout) ----------
__global__ __launch_bounds__(256) void k_out(const float* __restrict__ Wout,
                                             const float* __restrict__ bout,
                                             float* __restrict__ out, int N) {
    __shared__ float ws[64 * 40];
    __shared__ float bs[40];
    int tid = threadIdx.x;
    for (int i = tid; i < (64 * 40) / 4; i += 256)
        ((float4*)ws)[i] = ((const float4*)Wout)[i];
    if (tid < 40) bs[tid] = bout[tid];
    __syncthreads();

    int n = blockIdx.x * blockDim.x + tid;
    if (n >= N) return;

    unsigned long long acc2[20];
#pragma unroll
    for (int p = 0; p < 20; p++) acc2[p] = pack2(bs[2 * p], bs[2 * p + 1]);

    const float4* hr = ((const float4*)g_h) + (size_t)n * 16;
#pragma unroll 4
    for (int k4 = 0; k4 < 16; k4++) {
        float4 h4 = hr[k4];
        float hv[4] = {h4.x, h4.y, h4.z, h4.w};
#pragma unroll
        for (int j = 0; j < 4; j++) {
            int k = k4 * 4 + j;
            unsigned long long h2 = pack2(hv[j], hv[j]);
            const unsigned long long* wrow = (const unsigned long long*)&ws[k * 40];
#pragma unroll
            for (int p = 0; p < 20; p++) ffma2(acc2[p], h2, wrow[p]);
        }
    }

    float acc[40];
#pragma unroll
    for (int p = 0; p < 20; p++) unpack2(acc2[p], acc[2 * p], acc[2 * p + 1]);

    float m = acc[0];
#pragma unroll
    for (int c = 1; c < 40; c++) m = fmaxf(m, acc[c]);
    float s = 0.f;
#pragma unroll
    for (int c = 0; c < 40; c++) s += __expf(acc[c] - m);
    float ls = m + __logf(s);

    float4* o4 = (float4*)(out + (size_t)n * 40);
#pragma unroll
    for (int c4 = 0; c4 < 10; c4++) {
        float4 v;
        v.x = acc[c4 * 4 + 0] - ls;
        v.y = acc[c4 * 4 + 1] - ls;
        v.z = acc[c4 * 4 + 2] - ls;
        v.w = acc[c4 * 4 + 3] - ls;
        o4[c4] = v;
    }
}

// ---------- launch ----------
extern "C" void kernel_launch(void* const* d_in, const int* in_sizes, int n_in,
                              void* d_out, int out_size) {
    const float* x    = (const float*)d_in[0];
    const int*   ei   = (const int*)d_in[1];
    const float* W1   = (const float*)d_in[2];
    const float* b1   = (const float*)d_in[3];
    const float* relW = (const float*)d_in[4];
    const float* relb = (const float*)d_in[5];
    const float* Wout = (const float*)d_in[6];
    const float* bout = (const float*)d_in[7];
    const float* fuse = (const float*)d_in[8];
    float* out = (float*)d_out;

    const int N = in_sizes[0] / FIN;
    const int E = in_sizes[1] / 2;
    const int* src = ei;
    const int* dst = ei + E;

    const int smem_gemm1 = (64 * 128 + 128 * 64) * 4;               // 65536
    const int smem_layer = (64 * 64 + 64 * 64 + 64) * 4 + 64 * 4;   // 33280
    cudaFuncSetAttribute(k_gemm1, cudaFuncAttributeMaxDynamicSharedMemorySize, smem_gemm1);
    cudaFuncSetAttribute(k_layer, cudaFuncAttributeMaxDynamicSharedMemorySize, smem_layer);

    const int nbRows = (N + 63) / 64;

    float* hA;  cudaGetSymbolAddress((void**)&hA, g_h);
    float* hB;  cudaGetSymbolAddress((void**)&hB, g_hb);

    k_zero<<<(N + 255) / 256, 256>>>(N);
    k_bucket<<<((E / 2) + 255) / 256, 256>>>(src, dst, E);

    k_gemm1<<<nbRows, 256, smem_gemm1>>>(x, W1, b1, N);

    // layer 0: g_h -> g_hb
    k_layer<<<nbRows, 256, smem_layer>>>(hA, hB, relW, relb, fuse, 0, N);

    // layer 1: g_hb -> g_h
    k_layer<<<nbRows, 256, smem_layer>>>(hB, hA, relW, relb, fuse, 1, N);

    k_out<<<(N + 255) / 256, 256>>>(Wout, bout, out, N);
}

// round 10
// speedup vs baseline: 1.1137x; 1.1137x over previous
#include <cuda_runtime.h>
#include <math.h>

#define NMAX 200000
#define HID 64
#define FIN 128
#define NCLS 40
#define BKT 64   // neighbor bucket capacity per node

// ---------- scratch ----------
__device__ float g_h[NMAX * HID];    // hidden buffer A
__device__ float g_hb[NMAX * HID];   // hidden buffer B (double buffer)
__device__ float g_x1[NMAX * HID];   // x_first
__device__ int   g_cnt[NMAX];        // neighbor count (non-self in-degree)
__device__ int   g_bkt[NMAX * BKT];  // neighbor lists

// ---------- f32x2 helpers ----------
__device__ __forceinline__ unsigned long long pack2(float a, float b) {
    unsigned long long r;
    asm("mov.b64 %0, {%1, %2};" : "=l"(r) : "f"(a), "f"(b));
    return r;
}
__device__ __forceinline__ void unpack2(unsigned long long v, float& a, float& b) {
    asm("mov.b64 {%0, %1}, %2;" : "=f"(a), "=f"(b) : "l"(v));
}
__device__ __forceinline__ void ffma2(unsigned long long& d, unsigned long long a,
                                      unsigned long long b) {
    asm("fma.rn.f32x2 %0, %1, %2, %0;" : "+l"(d) : "l"(a), "l"(b));
}

// ---------- zero counters ----------
__global__ void k_zero(int N) {
    int i = blockIdx.x * blockDim.x + threadIdx.x;
    if (i < N) g_cnt[i] = 0;
}

// ---------- single-pass bucket build: 2 edges per thread ----------
__global__ __launch_bounds__(256) void k_bucket(const int* __restrict__ src,
                                                const int* __restrict__ dst, int E) {
    int t = blockIdx.x * blockDim.x + threadIdx.x;
    int e = t * 2;
    if (e >= E) return;
    int2 s2 = *(const int2*)&src[e];
    int2 d2 = *(const int2*)&dst[e];
    if (s2.x != d2.x) {
        int pos = atomicAdd(&g_cnt[d2.x], 1);
        if (pos < BKT) g_bkt[d2.x * BKT + pos] = s2.x;
    }
    if (e + 1 < E && s2.y != d2.y) {
        int pos = atomicAdd(&g_cnt[d2.y], 1);
        if (pos < BKT) g_bkt[d2.y * BKT + pos] = s2.y;
    }
}

// ---------- h = relu(x @ W1 + b1); seed x_first (64-row tile) ----------
__global__ __launch_bounds__(256) void k_gemm1(const float* __restrict__ x,
                                               const float* __restrict__ W1,
                                               const float* __restrict__ b1, int N) {
    extern __shared__ float sm[];
    float* xs = sm;                  // 64 x 128
    float* ws = sm + 64 * 128;       // 128 x 64
    const int tid = threadIdx.x;
    const int row0 = blockIdx.x * 64;

    for (int i = tid; i < (FIN * HID) / 4; i += 256)
        ((float4*)ws)[i] = ((const float4*)W1)[i];
    {
        int r = tid >> 5;            // 0..7
        int c4 = tid & 31;           // float4 col
        for (int j = 0; j < 8; j++) {
            int rr = r + j * 8;
            int g = row0 + rr;
            float4 v = (g < N) ? ((const float4*)x)[(size_t)g * 32 + c4]
                               : make_float4(0.f, 0.f, 0.f, 0.f);
            *(float4*)&xs[rr * 128 + c4 * 4] = v;
        }
    }
    __syncthreads();

    const int tr = tid >> 4, tc = tid & 15;
    const int r0 = tr * 4, c0 = tc * 4;
    unsigned long long acc2[4][2];
#pragma unroll
    for (int i = 0; i < 4; i++) { acc2[i][0] = 0ULL; acc2[i][1] = 0ULL; }

#pragma unroll 4
    for (int k = 0; k < FIN; k++) {
        ulonglong2 b2 = *(const ulonglong2*)&ws[k * HID + c0];
#pragma unroll
        for (int i = 0; i < 4; i++) {
            float a = xs[(r0 + i) * 128 + k];
            unsigned long long a2 = pack2(a, a);
            ffma2(acc2[i][0], a2, b2.x);
            ffma2(acc2[i][1], a2, b2.y);
        }
    }

    float4 bb = *(const float4*)&b1[c0];
#pragma unroll
    for (int i = 0; i < 4; i++) {
        int g = row0 + r0 + i;
        if (g < N) {
            float4 o;
            unpack2(acc2[i][0], o.x, o.y);
            unpack2(acc2[i][1], o.z, o.w);
            o.x = fmaxf(o.x + bb.x, 0.f);
            o.y = fmaxf(o.y + bb.y, 0.f);
            o.z = fmaxf(o.z + bb.z, 0.f);
            o.w = fmaxf(o.w + bb.w, 0.f);
            size_t idx = (size_t)g * 16 + (c0 >> 2);
            ((float4*)g_h)[idx] = o;
            ((float4*)g_x1)[idx] = o;
        }
    }
}

// ---------- fused layer (64-row tile): gather -> GEMM -> epilogue, fixup inline ----------
__global__ __launch_bounds__(256, 4) void k_layer(const float* __restrict__ h_in,
                                                  float* __restrict__ h_out,
                                                  const float* __restrict__ relW,
                                                  const float* __restrict__ relb,
                                                  const float* __restrict__ fuse,
                                                  int layer, int N) {
    extern __shared__ float sm[];
    float* as = sm;                    // 64 x 64 (agg tile)
    float* wsm = sm + 64 * 64;         // 64 x 64
    float* bsm = wsm + 64 * 64;        // 64
    int* dsm = (int*)(bsm + 64);       // 64
    const float* W5 = relW + ((size_t)(layer * 6 + 5)) * 64 * 64;
    const float* b5 = relb + (size_t)(layer * 6 + 5) * 64;
    const int tid = threadIdx.x;
    const int row0 = blockIdx.x * 64;

    for (int i = tid; i < (64 * 64) / 4; i += 256)
        ((float4*)wsm)[i] = ((const float4*)W5)[i];
    if (tid < 64) {
        bsm[tid] = b5[tid];
        int g = row0 + tid;
        dsm[tid] = (g < N) ? __ldg(&g_cnt[g]) : 0;
    }

    // gather phase: half-warp per node, int4 idx loads, 8-row value batches
    {
        const int hw = tid >> 4;    // 0..15
        const int c = tid & 15;     // float4 col
        const float4* h4 = (const float4*)h_in;
        for (int j = 0; j < 4; j++) {
            int rr = hw + j * 16;
            int g = row0 + rr;
            float4 acc = make_float4(0.f, 0.f, 0.f, 0.f);
            if (g < N) {
                acc = h4[(size_t)g * 16 + c];  // self
                const int* nb = &g_bkt[g * BKT];
                const int4* nb4 = (const int4*)nb;
                int cnt = min(__ldg(&g_cnt[g]), BKT);
                int i = 0;
                for (; i + 8 <= cnt; i += 8) {
                    int4 i0 = __ldg(&nb4[(i >> 2) + 0]);
                    int4 i1 = __ldg(&nb4[(i >> 2) + 1]);
                    float4 v0 = h4[(size_t)i0.x * 16 + c];
                    float4 v1 = h4[(size_t)i0.y * 16 + c];
                    float4 v2 = h4[(size_t)i0.z * 16 + c];
                    float4 v3 = h4[(size_t)i0.w * 16 + c];
                    float4 v4 = h4[(size_t)i1.x * 16 + c];
                    float4 v5 = h4[(size_t)i1.y * 16 + c];
                    float4 v6 = h4[(size_t)i1.z * 16 + c];
                    float4 v7 = h4[(size_t)i1.w * 16 + c];
                    acc.x += ((v0.x + v1.x) + (v2.x + v3.x)) + ((v4.x + v5.x) + (v6.x + v7.x));
                    acc.y += ((v0.y + v1.y) + (v2.y + v3.y)) + ((v4.y + v5.y) + (v6.y + v7.y));
                    acc.z += ((v0.z + v1.z) + (v2.z + v3.z)) + ((v4.z + v5.z) + (v6.z + v7.z));
                    acc.w += ((v0.w + v1.w) + (v2.w + v3.w)) + ((v4.w + v5.w) + (v6.w + v7.w));
                }
                for (; i + 4 <= cnt; i += 4) {
                    int4 i0 = __ldg(&nb4[i >> 2]);
                    float4 a = h4[(size_t)i0.x * 16 + c];
                    float4 b = h4[(size_t)i0.y * 16 + c];
                    float4 d = h4[(size_t)i0.z * 16 + c];
                    float4 e = h4[(size_t)i0.w * 16 + c];
                    acc.x += (a.x + b.x) + (d.x + e.x);
                    acc.y += (a.y + b.y) + (d.y + e.y);
                    acc.z += (a.z + b.z) + (d.z + e.z);
                    acc.w += (a.w + b.w) + (d.w + e.w);
                }
                for (; i < cnt; i++) {
                    int s0 = __ldg(&nb[i]);
                    float4 a = h4[(size_t)s0 * 16 + c];
                    acc.x += a.x; acc.y += a.y; acc.z += a.z; acc.w += a.w;
                }
            }
            *(float4*)&as[rr * 64 + c * 4] = acc;
        }
    }
    __syncthreads();

    const int tr = tid >> 4, tc = tid & 15;
    const int r0 = tr * 4, c0 = tc * 4;
    unsigned long long acc2[4][2];
#pragma unroll
    for (int i = 0; i < 4; i++) { acc2[i][0] = 0ULL; acc2[i][1] = 0ULL; }

#pragma unroll 4
    for (int k = 0; k < 64; k++) {
        ulonglong2 b2 = *(const ulonglong2*)&wsm[k * 64 + c0];
#pragma unroll
        for (int i = 0; i < 4; i++) {
            float a = as[(r0 + i) * 64 + k];
            unsigned long long a2 = pack2(a, a);
            ffma2(acc2[i][0], a2, b2.x);
            ffma2(acc2[i][1], a2, b2.y);
        }
    }

    float fv = fuse[layer];
    float4 bb = *(float4*)&bsm[c0];
#pragma unroll
    for (int i = 0; i < 4; i++) {
        int rr = r0 + i;
        int g = row0 + rr;
        if (g < N && dsm[rr] >= 5) {
            size_t idx = (size_t)g * 16 + (c0 >> 2);
            float4 xf = ((const float4*)g_x1)[idx];
            float4 o;
            unpack2(acc2[i][0], o.x, o.y);
            unpack2(acc2[i][1], o.z, o.w);
            o.x = o.x + bb.x + fv * xf.x;
            o.y = o.y + bb.y + fv * xf.y;
            o.z = o.z + bb.z + fv * xf.z;
            o.w = o.w + bb.w + fv * xf.w;
            ((float4*)h_out)[idx] = o;
        }
    }

    // inline fixup for rare deg<5 nodes (agg already in smem)
    if (tid < 64) {
        int g = row0 + tid;
        int d = dsm[tid];
        if (g < N && d < 5) {
            const float* W = relW + ((size_t)(layer * 6 + d)) * 64 * 64;
            const float* b = relb + (size_t)(layer * 6 + d) * 64;
            const float* arow = &as[tid * 64];
            for (int o = 0; o < 64; o++) {
                float s = b[o];
#pragma unroll 8
                for (int k = 0; k < 64; k++) s += arow[k] * W[k * 64 + o];
                h_out[(size_t)g * 64 + o] = s + fv * g_x1[(size_t)g * 64 + o];
            }
        }
    }
}

// ---------- output: log_softmax(h @ Wout + bout) ----------
__global__ __launch_bounds__(256) void k_out(const float* __restrict__ Wout,
                                             const float* __restrict__ bout,
                                             float* __restrict__ out, int N) {
    __shared__ float ws[64 * 40];
    __shared__ float bs[40];
    int tid = threadIdx.x;
    for (int i = tid; i < (64 * 40) / 4; i += 256)
        ((float4*)ws)[i] = ((const float4*)Wout)[i];
    if (tid < 40) bs[tid] = bout[tid];
    __syncthreads();

    int n = blockIdx.x * blockDim.x + tid;
    if (n >= N) return;

    unsigned long long acc2[20];
#pragma unroll
    for (int p = 0; p < 20; p++) acc2[p] = pack2(bs[2 * p], bs[2 * p + 1]);

    const float4* hr = ((const float4*)g_h) + (size_t)n * 16;
#pragma unroll 4
    for (int k4 = 0; k4 < 16; k4++) {
        float4 h4 = hr[k4];
        float hv[4] = {h4.x, h4.y, h4.z, h4.w};
#pragma unroll
        for (int j = 0; j < 4; j++) {
            int k = k4 * 4 + j;
            unsigned long long h2 = pack2(hv[j], hv[j]);
            const unsigned long long* wrow = (const unsigned long long*)&ws[k * 40];
#pragma unroll
            for (int p = 0; p < 20; p++) ffma2(acc2[p], h2, wrow[p]);
        }
    }

    float acc[40];
#pragma unroll
    for (int p = 0; p < 20; p++) unpack2(acc2[p], acc[2 * p], acc[2 * p + 1]);

    float m = acc[0];
#pragma unroll
    for (int c = 1; c < 40; c++) m = fmaxf(m, acc[c]);
    float s = 0.f;
#pragma unroll
    for (int c = 0; c < 40; c++) s += __expf(acc[c] - m);
    float ls = m + __logf(s);

    float4* o4 = (float4*)(out + (size_t)n * 40);
#pragma unroll
    for (int c4 = 0; c4 < 10; c4++) {
        float4 v;
        v.x = acc[c4 * 4 + 0] - ls;
        v.y = acc[c4 * 4 + 1] - ls;
        v.z = acc[c4 * 4 + 2] - ls;
        v.w = acc[c4 * 4 + 3] - ls;
        o4[c4] = v;
    }
}

// ---------- launch ----------
extern "C" void kernel_launch(void* const* d_in, const int* in_sizes, int n_in,
                              void* d_out, int out_size) {
    const float* x    = (const float*)d_in[0];
    const int*   ei   = (const int*)d_in[1];
    const float* W1   = (const float*)d_in[2];
    const float* b1   = (const float*)d_in[3];
    const float* relW = (const float*)d_in[4];
    const float* relb = (const float*)d_in[5];
    const float* Wout = (const float*)d_in[6];
    const float* bout = (const float*)d_in[7];
    const float* fuse = (const float*)d_in[8];
    float* out = (float*)d_out;

    const int N = in_sizes[0] / FIN;
    const int E = in_sizes[1] / 2;
    const int* src = ei;
    const int* dst = ei + E;

    const int smem_gemm1 = (64 * 128 + 128 * 64) * 4;               // 65536
    const int smem_layer = (64 * 64 + 64 * 64 + 64) * 4 + 64 * 4;   // 33280
    cudaFuncSetAttribute(k_gemm1, cudaFuncAttributeMaxDynamicSharedMemorySize, smem_gemm1);
    cudaFuncSetAttribute(k_layer, cudaFuncAttributeMaxDynamicSharedMemorySize, smem_layer);

    const int nbRows = (N + 63) / 64;

    float* hA;  cudaGetSymbolAddress((void**)&hA, g_h);
    float* hB;  cudaGetSymbolAddress((void**)&hB, g_hb);

    k_zero<<<(N + 255) / 256, 256>>>(N);
    k_bucket<<<((E / 2) + 255) / 256, 256>>>(src, dst, E);

    k_gemm1<<<nbRows, 256, smem_gemm1>>>(x, W1, b1, N);

    // layer 0: g_h -> g_hb
    k_layer<<<nbRows, 256, smem_layer>>>(hA, hB, relW, relb, fuse, 0, N);

    // layer 1: g_hb -> g_h
    k_layer<<<nbRows, 256, smem_layer>>>(hB, hA, relW, relb, fuse, 1, N);

    k_out<<<(N + 255) / 256, 256>>>(Wout, bout, out, N);
}

// round 11
// speedup vs baseline: 1.1180x; 1.0039x over previous
#include <cuda_runtime.h>
#include <math.h>

#define NMAX 200000
#define HID 64
#define FIN 128
#define NCLS 40
#define BKT 64   // neighbor bucket capacity per node

// ---------- scratch ----------
__device__ float g_h[NMAX * HID];    // hidden buffer A
__device__ float g_hb[NMAX * HID];   // hidden buffer B (double buffer)
__device__ float g_x1[NMAX * HID];   // x_first
__device__ int   g_cnt[NMAX];        // neighbor count (non-self in-degree)
__device__ int   g_bkt[NMAX * BKT];  // neighbor lists

// ---------- f32x2 helpers ----------
__device__ __forceinline__ unsigned long long pack2(float a, float b) {
    unsigned long long r;
    asm("mov.b64 %0, {%1, %2};" : "=l"(r) : "f"(a), "f"(b));
    return r;
}
__device__ __forceinline__ void unpack2(unsigned long long v, float& a, float& b) {
    asm("mov.b64 {%0, %1}, %2;" : "=f"(a), "=f"(b) : "l"(v));
}
__device__ __forceinline__ void ffma2(unsigned long long& d, unsigned long long a,
                                      unsigned long long b) {
    asm("fma.rn.f32x2 %0, %1, %2, %0;" : "+l"(d) : "l"(a), "l"(b));
}

// ---------- zero counters ----------
__global__ void k_zero(int N) {
    int i = blockIdx.x * blockDim.x + threadIdx.x;
    if (i < N) g_cnt[i] = 0;
}

// ---------- single-pass bucket build: 2 edges per thread ----------
__global__ __launch_bounds__(256) void k_bucket(const int* __restrict__ src,
                                                const int* __restrict__ dst, int E) {
    int t = blockIdx.x * blockDim.x + threadIdx.x;
    int e = t * 2;
    if (e >= E) return;
    int2 s2 = *(const int2*)&src[e];
    int2 d2 = *(const int2*)&dst[e];
    if (s2.x != d2.x) {
        int pos = atomicAdd(&g_cnt[d2.x], 1);
        if (pos < BKT) g_bkt[d2.x * BKT + pos] = s2.x;
    }
    if (e + 1 < E && s2.y != d2.y) {
        int pos = atomicAdd(&g_cnt[d2.y], 1);
        if (pos < BKT) g_bkt[d2.y * BKT + pos] = s2.y;
    }
}

// ---------- h = relu(x @ W1 + b1); seed x_first (64-row tile) ----------
__global__ __launch_bounds__(256) void k_gemm1(const float* __restrict__ x,
                                               const float* __restrict__ W1,
                                               const float* __restrict__ b1, int N) {
    extern __shared__ float sm[];
    float* xs = sm;                  // 64 x 128
    float* ws = sm + 64 * 128;       // 128 x 64
    const int tid = threadIdx.x;
    const int row0 = blockIdx.x * 64;

    for (int i = tid; i < (FIN * HID) / 4; i += 256)
        ((float4*)ws)[i] = ((const float4*)W1)[i];
    {
        int r = tid >> 5;            // 0..7
        int c4 = tid & 31;           // float4 col
        for (int j = 0; j < 8; j++) {
            int rr = r + j * 8;
            int g = row0 + rr;
            float4 v = (g < N) ? ((const float4*)x)[(size_t)g * 32 + c4]
                               : make_float4(0.f, 0.f, 0.f, 0.f);
            *(float4*)&xs[rr * 128 + c4 * 4] = v;
        }
    }
    __syncthreads();

    const int tr = tid >> 4, tc = tid & 15;
    const int r0 = tr * 4, c0 = tc * 4;
    unsigned long long acc2[4][2];
#pragma unroll
    for (int i = 0; i < 4; i++) { acc2[i][0] = 0ULL; acc2[i][1] = 0ULL; }

#pragma unroll 4
    for (int k = 0; k < FIN; k++) {
        ulonglong2 b2 = *(const ulonglong2*)&ws[k * HID + c0];
#pragma unroll
        for (int i = 0; i < 4; i++) {
            float a = xs[(r0 + i) * 128 + k];
            unsigned long long a2 = pack2(a, a);
            ffma2(acc2[i][0], a2, b2.x);
            ffma2(acc2[i][1], a2, b2.y);
        }
    }

    float4 bb = *(const float4*)&b1[c0];
#pragma unroll
    for (int i = 0; i < 4; i++) {
        int g = row0 + r0 + i;
        if (g < N) {
            float4 o;
            unpack2(acc2[i][0], o.x, o.y);
            unpack2(acc2[i][1], o.z, o.w);
            o.x = fmaxf(o.x + bb.x, 0.f);
            o.y = fmaxf(o.y + bb.y, 0.f);
            o.z = fmaxf(o.z + bb.z, 0.f);
            o.w = fmaxf(o.w + bb.w, 0.f);
            size_t idx = (size_t)g * 16 + (c0 >> 2);
            ((float4*)g_h)[idx] = o;
            ((float4*)g_x1)[idx] = o;
        }
    }
}

// ---------- fused layer (64-row tile): gather -> GEMM -> epilogue, fixup inline ----------
__global__ __launch_bounds__(256, 4) void k_layer(const float* __restrict__ h_in,
                                                  float* __restrict__ h_out,
                                                  const float* __restrict__ relW,
                                                  const float* __restrict__ relb,
                                                  const float* __restrict__ fuse,
                                                  int layer, int N) {
    extern __shared__ float sm[];
    float* as = sm;                    // 64 x 64 (agg tile)
    float* wsm = sm + 64 * 64;         // 64 x 64
    float* bsm = wsm + 64 * 64;        // 64
    int* dsm = (int*)(bsm + 64);       // 64
    const float* W5 = relW + ((size_t)(layer * 6 + 5)) * 64 * 64;
    const float* b5 = relb + (size_t)(layer * 6 + 5) * 64;
    const int tid = threadIdx.x;
    const int row0 = blockIdx.x * 64;

    for (int i = tid; i < (64 * 64) / 4; i += 256)
        ((float4*)wsm)[i] = ((const float4*)W5)[i];
    if (tid < 64) {
        bsm[tid] = b5[tid];
        int g = row0 + tid;
        dsm[tid] = (g < N) ? __ldg(&g_cnt[g]) : 0;
    }

    // gather phase: half-warp per node, 8-row batches with index double-buffering
    {
        const int hw = tid >> 4;    // 0..15
        const int c = tid & 15;     // float4 col
        const float4* h4 = (const float4*)h_in;
        for (int j = 0; j < 4; j++) {
            int rr = hw + j * 16;
            int g = row0 + rr;
            float4 acc = make_float4(0.f, 0.f, 0.f, 0.f);
            if (g < N) {
                acc = h4[(size_t)g * 16 + c];  // self
                const int* nb = &g_bkt[g * BKT];
                const int4* nb4 = (const int4*)nb;
                int cnt = min(__ldg(&g_cnt[g]), BKT);
                int i = 0;
                if (cnt >= 8) {
                    // prefetch first batch's indices
                    int4 ia = __ldg(&nb4[0]);
                    int4 ib = __ldg(&nb4[1]);
                    while (i + 8 <= cnt) {
                        int4 n0 = ia, n1 = ib;
                        int inext = i + 8;
                        if (inext + 8 <= cnt) {   // prefetch next batch's indices
                            ia = __ldg(&nb4[(inext >> 2) + 0]);
                            ib = __ldg(&nb4[(inext >> 2) + 1]);
                        }
                        float4 v0 = h4[(size_t)n0.x * 16 + c];
                        float4 v1 = h4[(size_t)n0.y * 16 + c];
                        float4 v2 = h4[(size_t)n0.z * 16 + c];
                        float4 v3 = h4[(size_t)n0.w * 16 + c];
                        float4 v4 = h4[(size_t)n1.x * 16 + c];
                        float4 v5 = h4[(size_t)n1.y * 16 + c];
                        float4 v6 = h4[(size_t)n1.z * 16 + c];
                        float4 v7 = h4[(size_t)n1.w * 16 + c];
                        acc.x += ((v0.x + v1.x) + (v2.x + v3.x)) + ((v4.x + v5.x) + (v6.x + v7.x));
                        acc.y += ((v0.y + v1.y) + (v2.y + v3.y)) + ((v4.y + v5.y) + (v6.y + v7.y));
                        acc.z += ((v0.z + v1.z) + (v2.z + v3.z)) + ((v4.z + v5.z) + (v6.z + v7.z));
                        acc.w += ((v0.w + v1.w) + (v2.w + v3.w)) + ((v4.w + v5.w) + (v6.w + v7.w));
                        i = inext;
                    }
                }
                for (; i + 4 <= cnt; i += 4) {
                    int4 i0 = __ldg(&nb4[i >> 2]);
                    float4 a = h4[(size_t)i0.x * 16 + c];
                    float4 b = h4[(size_t)i0.y * 16 + c];
                    float4 d = h4[(size_t)i0.z * 16 + c];
                    float4 e = h4[(size_t)i0.w * 16 + c];
                    acc.x += (a.x + b.x) + (d.x + e.x);
                    acc.y += (a.y + b.y) + (d.y + e.y);
                    acc.z += (a.z + b.z) + (d.z + e.z);
                    acc.w += (a.w + b.w) + (d.w + e.w);
                }
                for (; i < cnt; i++) {
                    int s0 = __ldg(&nb[i]);
                    float4 a = h4[(size_t)s0 * 16 + c];
                    acc.x += a.x; acc.y += a.y; acc.z += a.z; acc.w += a.w;
                }
            }
            *(float4*)&as[rr * 64 + c * 4] = acc;
        }
    }
    __syncthreads();

    const int tr = tid >> 4, tc = tid & 15;
    const int r0 = tr * 4, c0 = tc * 4;
    unsigned long long acc2[4][2];
#pragma unroll
    for (int i = 0; i < 4; i++) { acc2[i][0] = 0ULL; acc2[i][1] = 0ULL; }

#pragma unroll 4
    for (int k = 0; k < 64; k++) {
        ulonglong2 b2 = *(const ulonglong2*)&wsm[k * 64 + c0];
#pragma unroll
        for (int i = 0; i < 4; i++) {
            float a = as[(r0 + i) * 64 + k];
            unsigned long long a2 = pack2(a, a);
            ffma2(acc2[i][0], a2, b2.x);
            ffma2(acc2[i][1], a2, b2.y);
        }
    }

    float fv = fuse[layer];
    float4 bb = *(float4*)&bsm[c0];
#pragma unroll
    for (int i = 0; i < 4; i++) {
        int rr = r0 + i;
        int g = row0 + rr;
        if (g < N && dsm[rr] >= 5) {
            size_t idx = (size_t)g * 16 + (c0 >> 2);
            float4 xf = ((const float4*)g_x1)[idx];
            float4 o;
            unpack2(acc2[i][0], o.x, o.y);
            unpack2(acc2[i][1], o.z, o.w);
            o.x = o.x + bb.x + fv * xf.x;
            o.y = o.y + bb.y + fv * xf.y;
            o.z = o.z + bb.z + fv * xf.z;
            o.w = o.w + bb.w + fv * xf.w;
            ((float4*)h_out)[idx] = o;
        }
    }

    // inline fixup for rare deg<5 nodes (agg already in smem)
    if (tid < 64) {
        int g = row0 + tid;
        int d = dsm[tid];
        if (g < N && d < 5) {
            const float* W = relW + ((size_t)(layer * 6 + d)) * 64 * 64;
            const float* b = relb + (size_t)(layer * 6 + d) * 64;
            const float* arow = &as[tid * 64];
            for (int o = 0; o < 64; o++) {
                float s = b[o];
#pragma unroll 8
                for (int k = 0; k < 64; k++) s += arow[k] * W[k * 64 + o];
                h_out[(size_t)g * 64 + o] = s + fv * g_x1[(size_t)g * 64 + o];
            }
        }
    }
}

// ---------- output: log_softmax(h @ Wout + bout) ----------
__global__ __launch_bounds__(256) void k_out(const float* __restrict__ Wout,
                                             const float* __restrict__ bout,
                                             float* __restrict__ out, int N) {
    __shared__ float ws[64 * 40];
    __shared__ float bs[40];
    int tid = threadIdx.x;
    for (int i = tid; i < (64 * 40) / 4; i += 256)
        ((float4*)ws)[i] = ((const float4*)Wout)[i];
    if (tid < 40) bs[tid] = bout[tid];
    __syncthreads();

    int n = blockIdx.x * blockDim.x + tid;
    if (n >= N) return;

    unsigned long long acc2[20];
#pragma unroll
    for (int p = 0; p < 20; p++) acc2[p] = pack2(bs[2 * p], bs[2 * p + 1]);

    const float4* hr = ((const float4*)g_h) + (size_t)n * 16;
#pragma unroll 4
    for (int k4 = 0; k4 < 16; k4++) {
        float4 h4 = hr[k4];
        float hv[4] = {h4.x, h4.y, h4.z, h4.w};
#pragma unroll
        for (int j = 0; j < 4; j++) {
            int k = k4 * 4 + j;
            unsigned long long h2 = pack2(hv[j], hv[j]);
            const unsigned long long* wrow = (const unsigned long long*)&ws[k * 40];
#pragma unroll
            for (int p = 0; p < 20; p++) ffma2(acc2[p], h2, wrow[p]);
        }
    }

    float acc[40];
#pragma unroll
    for (int p = 0; p < 20; p++) unpack2(acc2[p], acc[2 * p], acc[2 * p + 1]);

    float m = acc[0];
#pragma unroll
    for (int c = 1; c < 40; c++) m = fmaxf(m, acc[c]);
    float s = 0.f;
#pragma unroll
    for (int c = 0; c < 40; c++) s += __expf(acc[c] - m);
    float ls = m + __logf(s);

    float4* o4 = (float4*)(out + (size_t)n * 40);
#pragma unroll
    for (int c4 = 0; c4 < 10; c4++) {
        float4 v;
        v.x = acc[c4 * 4 + 0] - ls;
        v.y = acc[c4 * 4 + 1] - ls;
        v.z = acc[c4 * 4 + 2] - ls;
        v.w = acc[c4 * 4 + 3] - ls;
        o4[c4] = v;
    }
}

// ---------- launch ----------
extern "C" void kernel_launch(void* const* d_in, const int* in_sizes, int n_in,
                              void* d_out, int out_size) {
    const float* x    = (const float*)d_in[0];
    const int*   ei   = (const int*)d_in[1];
    const float* W1   = (const float*)d_in[2];
    const float* b1   = (const float*)d_in[3];
    const float* relW = (const float*)d_in[4];
    const float* relb = (const float*)d_in[5];
    const float* Wout = (const float*)d_in[6];
    const float* bout = (const float*)d_in[7];
    const float* fuse = (const float*)d_in[8];
    float* out = (float*)d_out;

    const int N = in_sizes[0] / FIN;
    const int E = in_sizes[1] / 2;
    const int* src = ei;
    const int* dst = ei + E;

    const int smem_gemm1 = (64 * 128 + 128 * 64) * 4;               // 65536
    const int smem_layer = (64 * 64 + 64 * 64 + 64) * 4 + 64 * 4;   // 33280
    cudaFuncSetAttribute(k_gemm1, cudaFuncAttributeMaxDynamicSharedMemorySize, smem_gemm1);
    cudaFuncSetAttribute(k_layer, cudaFuncAttributeMaxDynamicSharedMemorySize, smem_layer);

    const int nbRows = (N + 63) / 64;

    float* hA;  cudaGetSymbolAddress((void**)&hA, g_h);
    float* hB;  cudaGetSymbolAddress((void**)&hB, g_hb);

    k_zero<<<(N + 255) / 256, 256>>>(N);
    k_bucket<<<((E / 2) + 255) / 256, 256>>>(src, dst, E);

    k_gemm1<<<nbRows, 256, smem_gemm1>>>(x, W1, b1, N);

    // layer 0: g_h -> g_hb
    k_layer<<<nbRows, 256, smem_layer>>>(hA, hB, relW, relb, fuse, 0, N);

    // layer 1: g_hb -> g_h
    k_layer<<<nbRows, 256, smem_layer>>>(hB, hA, relW, relb, fuse, 1, N);

    k_out<<<(N + 255) / 256, 256>>>(Wout, bout, out, N);
}